// round 13
// baseline (speedup 1.0000x reference)
#include <cuda_runtime.h>
#include <cuda_bf16.h>
#include <mma.h>
#include <math.h>
#include <stdint.h>

using namespace nvcuda;

#define NUM_NEURONS 2048
#define D_MODEL     1024
#define BATCH       64
#define K_TOTAL     4096
#define KSPLIT      32
#define DCHUNK      128

// GEMM tiling
#define KK        32                          // k per stage
#define NSTAGE    ((K_TOTAL / KSPLIT) / KK)   // 4
#define LDM       40                          // padded row stride (bf16), 80B
#define OFF_AL    (64 * LDM)
#define OFF_BH    (2 * 64 * LDM)
#define OFF_BL    (OFF_BH + 128 * LDM)
#define STAGE_EL  (OFF_BL + 128 * LDM)        // 15360 bf16 per stage
#define SMEM_B    (2 * STAGE_EL * 2)          // 61440 bytes

// Scratch (static device globals — no runtime allocation)
__device__ __align__(256) float g_xT[D_MODEL * BATCH];
__device__ __align__(256) __nv_bfloat16 g_Ahi[BATCH * K_TOTAL];    // S^T hi [b][k]
__device__ __align__(256) __nv_bfloat16 g_Alo[BATCH * K_TOTAL];    // S^T lo
__device__ __align__(256) __nv_bfloat16 g_Phi[D_MODEL * K_TOTAL];  // Pcat hi [j][k]
__device__ __align__(256) __nv_bfloat16 g_Plo[D_MODEL * K_TOTAL];  // Pcat lo
__device__ __align__(256) float g_part[KSPLIT * BATCH * D_MODEL];  // 8MB

// ---------------------------------------------------------------------------
__global__ void prep_x(const float* __restrict__ x) {
    int i = blockIdx.x * 256 + threadIdx.x;
    g_xT[(i & 1023) * BATCH + (i >> 10)] = x[i];
}

// Split Pcat rows [j][k] into bf16 hi/lo (side stream, hidden under main).
__global__ __launch_bounds__(256) void prep_P(const float* __restrict__ Pr,
                                              const float* __restrict__ Pi) {
    #pragma unroll
    for (int it = 0; it < 4; it++) {
        int idx = blockIdx.x * 256 + threadIdx.x + it * (4096 * 256);
        int j = idx >> 12, k = idx & 4095;
        float v = (k < NUM_NEURONS) ? Pr[j * NUM_NEURONS + k]
                                    : Pi[j * NUM_NEURONS + k - NUM_NEURONS];
        __nv_bfloat16 h = __float2bfloat16(v);
        g_Phi[idx] = h;
        g_Plo[idx] = __float2bfloat16(v - __bfloat162float(h));
    }
}

// ---------------------------------------------------------------------------
// FMA-pipe sincos (R3-proven).
// ---------------------------------------------------------------------------
__device__ __forceinline__ void sincos_poly(float th, float& s_out, float& c_out) {
    const float TWO_OVER_PI = 0.636619772f;
    const float MAGIC = 12582912.0f;
    float w   = th * TWO_OVER_PI;
    float big = w + MAGIC;
    int   qi  = __float_as_int(big);
    float r   = big - MAGIC;
    float u   = w - r;
    float u2  = u * u;
    float sp  = fmaf(u2, fmaf(u2, fmaf(u2, -4.6817541e-3f, 7.9692626e-2f),
                              -6.4596410e-1f), 1.57079633f) * u;
    float cp  = fmaf(u2, fmaf(u2, fmaf(u2, -2.0864648e-2f, 2.5369510e-1f),
                              -1.2337006f), 1.0f);
    float ss = (qi & 1) ? cp : sp;
    float cc = (qi & 1) ? sp : cp;
    if (qi & 2)       ss = -ss;
    if ((qi + 1) & 2) cc = -cc;
    s_out = ss; c_out = cc;
}

// ---------------------------------------------------------------------------
// Main (R3-proven core). NEW: writes bf16 hi/lo S^T directly (fuses the old
// s_convert kernel — scattered 2B stores, ~16MB sector traffic, << 4.4us).
// cos row: k = n; sin row: k = n + 2048.
// ---------------------------------------------------------------------------
__global__ __launch_bounds__(128) void resonant_main(const float* __restrict__ t,
                                                     const float* __restrict__ W,
                                                     const float* __restrict__ Bp) {
    __shared__ float  x_sh[DCHUNK][BATCH];
    __shared__ float2 rB_sh[2][DCHUNK];

    int tid = threadIdx.x;
    int b   = tid & 63;
    int nl  = tid >> 6;
    int n0  = blockIdx.x * 2;

    float tb = t[b];
    float cs = 0.0f, sn = 0.0f;

    for (int d0 = 0; d0 < D_MODEL; d0 += DCHUNK) {
        float4*       xs4 = reinterpret_cast<float4*>(&x_sh[0][0]);
        const float4* xg4 = reinterpret_cast<const float4*>(g_xT + d0 * BATCH);
        #pragma unroll
        for (int i = 0; i < (DCHUNK * BATCH / 4) / 128; i++)
            xs4[tid + i * 128] = xg4[tid + i * 128];
        {
            float w0 = W [(n0 + 0) * D_MODEL + d0 + tid];
            float p0 = Bp[(n0 + 0) * D_MODEL + d0 + tid];
            rB_sh[0][tid] = make_float2(__fdividef(1.0f, 1.0f + fabsf(w0)), p0);
            float w1 = W [(n0 + 1) * D_MODEL + d0 + tid];
            float p1 = Bp[(n0 + 1) * D_MODEL + d0 + tid];
            rB_sh[1][tid] = make_float2(__fdividef(1.0f, 1.0f + fabsf(w1)), p1);
        }
        __syncthreads();

        #pragma unroll
        for (int dd = 0; dd < DCHUNK; dd += 4) {
            #pragma unroll
            for (int j = 0; j < 3; j++) {
                float2 rb = rB_sh[nl][dd + j];
                float th  = fmaf(x_sh[dd + j][b], rb.x, rb.y) + tb;
                float s, c;
                __sincosf(th, &s, &c);
                cs += c; sn += s;
            }
            {
                float2 rb = rB_sh[nl][dd + 3];
                float th  = fmaf(x_sh[dd + 3][b], rb.x, rb.y) + tb;
                float s, c;
                sincos_poly(th, s, c);
                cs += c; sn += s;
            }
        }
        __syncthreads();
    }

    int n = n0 + nl;
    __nv_bfloat16 ch = __float2bfloat16(cs);
    g_Ahi[b * K_TOTAL + n] = ch;
    g_Alo[b * K_TOTAL + n] = __float2bfloat16(cs - __bfloat162float(ch));
    __nv_bfloat16 sh = __float2bfloat16(sn);
    g_Ahi[b * K_TOTAL + n + NUM_NEURONS] = sh;
    g_Alo[b * K_TOTAL + n + NUM_NEURONS] = __float2bfloat16(sn - __bfloat162float(sh));
}

// ---------------------------------------------------------------------------
// Tensor-core GEMM, smem-staged + double buffer + reg prefetch (R12-proven),
// now KSPLIT=32 -> grid (8,32)=256 CTAs (R12's 128 left 20 SMs idle).
// CTA = 64b x 128j, 8 warps of 32x32 (2x2 frags), 4 stages of KK=32.
// bf16 hi/lo split: hi*hi + lo*hi + hi*lo, fp32 acc. Disjoint partials.
// ---------------------------------------------------------------------------
__global__ __launch_bounds__(256) void gemm_wmma() {
    extern __shared__ __nv_bfloat16 sm[];

    int tid  = threadIdx.x;
    int warp = tid >> 5;
    int wb   = (warp >> 2) * 32;
    int wj   = (warp & 3) * 32;
    int j0   = blockIdx.x * 128;
    int k0   = blockIdx.y * (K_TOTAL / KSPLIT);   // 128 per CTA

    int arow = tid >> 2, achk = (tid & 3) * 8;
    const __nv_bfloat16* gAh = g_Ahi + arow * K_TOTAL + k0 + achk;
    const __nv_bfloat16* gAl = g_Alo + arow * K_TOTAL + k0 + achk;
    int brow0 = tid >> 1, bchk0 = (tid & 1) * 16;
    const __nv_bfloat16* gBh = g_Phi + (j0 + brow0) * K_TOTAL + k0 + bchk0;
    const __nv_bfloat16* gBl = g_Plo + (j0 + brow0) * K_TOTAL + k0 + bchk0;

    uint32_t aDst = arow * LDM + achk;
    uint32_t bDst = brow0 * LDM + bchk0;

    wmma::fragment<wmma::matrix_a, 16, 16, 16, __nv_bfloat16, wmma::row_major> aH[2], aL[2];
    wmma::fragment<wmma::matrix_b, 16, 16, 16, __nv_bfloat16, wmma::col_major> bH[2], bL[2];
    wmma::fragment<wmma::accumulator, 16, 16, 16, float> c[2][2];
    #pragma unroll
    for (int i = 0; i < 2; i++)
        #pragma unroll
        for (int j = 0; j < 2; j++) wmma::fill_fragment(c[i][j], 0.0f);

    {   // stage 0: global -> smem
        __nv_bfloat16* st = sm;
        *reinterpret_cast<uint4*>(st + aDst)          = *reinterpret_cast<const uint4*>(gAh);
        *reinterpret_cast<uint4*>(st + OFF_AL + aDst) = *reinterpret_cast<const uint4*>(gAl);
        #pragma unroll
        for (int q = 0; q < 2; q++) {
            *reinterpret_cast<uint4*>(st + OFF_BH + bDst + q * 8) =
                *reinterpret_cast<const uint4*>(gBh + q * 8);
            *reinterpret_cast<uint4*>(st + OFF_BL + bDst + q * 8) =
                *reinterpret_cast<const uint4*>(gBl + q * 8);
        }
    }
    __syncthreads();

    uint4 rAh, rAl, rBh[2], rBl[2];

    for (int s = 0; s < NSTAGE; s++) {
        if (s + 1 < NSTAGE) {             // prefetch next stage into regs
            int off = (s + 1) * KK;
            rAh = *reinterpret_cast<const uint4*>(gAh + off);
            rAl = *reinterpret_cast<const uint4*>(gAl + off);
            #pragma unroll
            for (int q = 0; q < 2; q++) {
                rBh[q] = *reinterpret_cast<const uint4*>(gBh + off + q * 8);
                rBl[q] = *reinterpret_cast<const uint4*>(gBl + off + q * 8);
            }
        }

        const __nv_bfloat16* st = sm + (s & 1) * STAGE_EL;
        #pragma unroll
        for (int ks = 0; ks < 2; ks++) {
            int kc = ks * 16;
            wmma::load_matrix_sync(aH[0], st + (wb +  0) * LDM + kc, LDM);
            wmma::load_matrix_sync(aH[1], st + (wb + 16) * LDM + kc, LDM);
            wmma::load_matrix_sync(aL[0], st + OFF_AL + (wb +  0) * LDM + kc, LDM);
            wmma::load_matrix_sync(aL[1], st + OFF_AL + (wb + 16) * LDM + kc, LDM);
            wmma::load_matrix_sync(bH[0], st + OFF_BH + (wj +  0) * LDM + kc, LDM);
            wmma::load_matrix_sync(bH[1], st + OFF_BH + (wj + 16) * LDM + kc, LDM);
            wmma::load_matrix_sync(bL[0], st + OFF_BL + (wj +  0) * LDM + kc, LDM);
            wmma::load_matrix_sync(bL[1], st + OFF_BL + (wj + 16) * LDM + kc, LDM);
            #pragma unroll
            for (int i = 0; i < 2; i++)
                #pragma unroll
                for (int j = 0; j < 2; j++) {
                    wmma::mma_sync(c[i][j], aH[i], bH[j], c[i][j]);
                    wmma::mma_sync(c[i][j], aL[i], bH[j], c[i][j]);
                    wmma::mma_sync(c[i][j], aH[i], bL[j], c[i][j]);
                }
        }

        if (s + 1 < NSTAGE) {
            __syncthreads();
            __nv_bfloat16* dt = sm + ((s + 1) & 1) * STAGE_EL;
            *reinterpret_cast<uint4*>(dt + aDst)          = rAh;
            *reinterpret_cast<uint4*>(dt + OFF_AL + aDst) = rAl;
            #pragma unroll
            for (int q = 0; q < 2; q++) {
                *reinterpret_cast<uint4*>(dt + OFF_BH + bDst + q * 8) = rBh[q];
                *reinterpret_cast<uint4*>(dt + OFF_BL + bDst + q * 8) = rBl[q];
            }
            __syncthreads();
        }
    }

    float* dst = g_part + blockIdx.y * (BATCH * D_MODEL);
    #pragma unroll
    for (int i = 0; i < 2; i++)
        #pragma unroll
        for (int j = 0; j < 2; j++)
            wmma::store_matrix_sync(dst + (wb + i * 16) * D_MODEL + j0 + wj + j * 16,
                                    c[i][j], D_MODEL, wmma::mem_row_major);
}

// ---------------------------------------------------------------------------
// Epilogue: reduce KSPLIT=32 partials + SiLU (R3-proven 256x256 config).
// ---------------------------------------------------------------------------
__global__ __launch_bounds__(256) void epilogue(float* __restrict__ out) {
    int i = blockIdx.x * 256 + threadIdx.x;
    float s = 0.0f;
    #pragma unroll
    for (int ks = 0; ks < KSPLIT; ks++)
        s += g_part[ks * (BATCH * D_MODEL) + i];
    out[i] = s / (1.0f + expf(-s));
}

// ---------------------------------------------------------------------------
// Capture-safe fork/join (R11-proven). Inputs: x, t, W, B_p, Pr, Pi, tables.
// ---------------------------------------------------------------------------
extern "C" void kernel_launch(void* const* d_in, const int* in_sizes, int n_in,
                              void* d_out, int out_size) {
    const float* x  = (const float*)d_in[0];
    const float* t  = (const float*)d_in[1];
    const float* W  = (const float*)d_in[2];
    const float* Bp = (const float*)d_in[3];
    const float* Pr = (const float*)d_in[4];
    const float* Pi = (const float*)d_in[5];
    float* out = (float*)d_out;

    static cudaStream_t s1 = nullptr;
    static cudaEvent_t  evFork, evP;
    if (!s1) {
        cudaStreamCreateWithFlags(&s1, cudaStreamNonBlocking);
        cudaEventCreateWithFlags(&evFork, cudaEventDisableTiming);
        cudaEventCreateWithFlags(&evP,    cudaEventDisableTiming);
        cudaFuncSetAttribute(gemm_wmma, cudaFuncAttributeMaxDynamicSharedMemorySize, SMEM_B);
    }

    cudaEventRecord(evFork, 0);
    cudaStreamWaitEvent(s1, evFork, 0);
    prep_P<<<4096, 256, 0, s1>>>(Pr, Pi);
    cudaEventRecord(evP, s1);

    prep_x<<<(BATCH * D_MODEL + 255) / 256, 256>>>(x);
    resonant_main<<<NUM_NEURONS / 2, 128>>>(t, W, Bp);

    cudaStreamWaitEvent(0, evP, 0);
    gemm_wmma<<<dim3(D_MODEL / 128, KSPLIT), 256, SMEM_B>>>();
    epilogue<<<(BATCH * D_MODEL + 255) / 256, 256>>>(out);
}

// round 14
// speedup vs baseline: 1.0732x; 1.0732x over previous
#include <cuda_runtime.h>
#include <cuda_bf16.h>
#include <mma.h>
#include <math.h>
#include <stdint.h>

using namespace nvcuda;

#define NUM_NEURONS 2048
#define D_MODEL     1024
#define BATCH       64
#define K_TOTAL     4096
#define KSPLIT      32
#define DCHUNK      128

// GEMM tiling
#define KK        32                          // k per stage
#define NSTAGE    ((K_TOTAL / KSPLIT) / KK)   // 4
#define LDM       40                          // padded row stride (bf16), 80B
#define OFF_AL    (64 * LDM)
#define OFF_BH    (2 * 64 * LDM)
#define OFF_BL    (OFF_BH + 128 * LDM)
#define STAGE_EL  (OFF_BL + 128 * LDM)        // 15360 bf16 per stage
#define SMEM_B    (2 * STAGE_EL * 2)          // 61440 bytes

// Scratch (static device globals — no runtime allocation)
__device__ __align__(256) float g_xT[D_MODEL * BATCH];
__device__ __align__(256) __nv_bfloat16 g_Ahi[BATCH * K_TOTAL];    // S^T hi [b][k]
__device__ __align__(256) __nv_bfloat16 g_Alo[BATCH * K_TOTAL];    // S^T lo
__device__ __align__(256) float g_part[KSPLIT * BATCH * D_MODEL];  // 8MB

// ---------------------------------------------------------------------------
__global__ void prep_x(const float* __restrict__ x) {
    int i = blockIdx.x * 256 + threadIdx.x;
    g_xT[(i & 1023) * BATCH + (i >> 10)] = x[i];
}

// ---------------------------------------------------------------------------
// FMA-pipe sincos (R3-proven).
// ---------------------------------------------------------------------------
__device__ __forceinline__ void sincos_poly(float th, float& s_out, float& c_out) {
    const float TWO_OVER_PI = 0.636619772f;
    const float MAGIC = 12582912.0f;
    float w   = th * TWO_OVER_PI;
    float big = w + MAGIC;
    int   qi  = __float_as_int(big);
    float r   = big - MAGIC;
    float u   = w - r;
    float u2  = u * u;
    float sp  = fmaf(u2, fmaf(u2, fmaf(u2, -4.6817541e-3f, 7.9692626e-2f),
                              -6.4596410e-1f), 1.57079633f) * u;
    float cp  = fmaf(u2, fmaf(u2, fmaf(u2, -2.0864648e-2f, 2.5369510e-1f),
                              -1.2337006f), 1.0f);
    float ss = (qi & 1) ? cp : sp;
    float cc = (qi & 1) ? sp : cp;
    if (qi & 2)       ss = -ss;
    if ((qi + 1) & 2) cc = -cc;
    s_out = ss; c_out = cc;
}

// ---------------------------------------------------------------------------
// Main (R3-proven core + rotation identity): accumulate over phi = x*r + B_p
// (NO per-element +t), then rotate once per thread:
//   sum cos(phi+t) = cos t * sum cos phi - sin t * sum sin phi   (exact)
// Writes bf16 hi/lo S^T directly (fused s_convert, R13-proven).
// ---------------------------------------------------------------------------
__global__ __launch_bounds__(128) void resonant_main(const float* __restrict__ t,
                                                     const float* __restrict__ W,
                                                     const float* __restrict__ Bp) {
    __shared__ float  x_sh[DCHUNK][BATCH];
    __shared__ float2 rB_sh[2][DCHUNK];

    int tid = threadIdx.x;
    int b   = tid & 63;
    int nl  = tid >> 6;
    int n0  = blockIdx.x * 2;

    float tb = t[b];
    float cp = 0.0f, sp = 0.0f;     // sums of cos(phi), sin(phi)

    for (int d0 = 0; d0 < D_MODEL; d0 += DCHUNK) {
        float4*       xs4 = reinterpret_cast<float4*>(&x_sh[0][0]);
        const float4* xg4 = reinterpret_cast<const float4*>(g_xT + d0 * BATCH);
        #pragma unroll
        for (int i = 0; i < (DCHUNK * BATCH / 4) / 128; i++)
            xs4[tid + i * 128] = xg4[tid + i * 128];
        {
            float w0 = W [(n0 + 0) * D_MODEL + d0 + tid];
            float p0 = Bp[(n0 + 0) * D_MODEL + d0 + tid];
            rB_sh[0][tid] = make_float2(__fdividef(1.0f, 1.0f + fabsf(w0)), p0);
            float w1 = W [(n0 + 1) * D_MODEL + d0 + tid];
            float p1 = Bp[(n0 + 1) * D_MODEL + d0 + tid];
            rB_sh[1][tid] = make_float2(__fdividef(1.0f, 1.0f + fabsf(w1)), p1);
        }
        __syncthreads();

        #pragma unroll
        for (int dd = 0; dd < DCHUNK; dd += 4) {
            #pragma unroll
            for (int j = 0; j < 3; j++) {
                float2 rb = rB_sh[nl][dd + j];
                float th  = fmaf(x_sh[dd + j][b], rb.x, rb.y);
                float s, c;
                __sincosf(th, &s, &c);
                cp += c; sp += s;
            }
            {
                float2 rb = rB_sh[nl][dd + 3];
                float th  = fmaf(x_sh[dd + 3][b], rb.x, rb.y);
                float s, c;
                sincos_poly(th, s, c);
                cp += c; sp += s;
            }
        }
        __syncthreads();
    }

    // rotate by t_b (exact identity), once per thread
    float st_, ct_;
    __sincosf(tb, &st_, &ct_);
    float cs = ct_ * cp - st_ * sp;
    float sn = st_ * cp + ct_ * sp;

    int n = n0 + nl;
    __nv_bfloat16 ch = __float2bfloat16(cs);
    g_Ahi[b * K_TOTAL + n] = ch;
    g_Alo[b * K_TOTAL + n] = __float2bfloat16(cs - __bfloat162float(ch));
    __nv_bfloat16 sh = __float2bfloat16(sn);
    g_Ahi[b * K_TOTAL + n + NUM_NEURONS] = sh;
    g_Alo[b * K_TOTAL + n + NUM_NEURONS] = __float2bfloat16(sn - __bfloat162float(sh));
}

// ---------------------------------------------------------------------------
// bf16 hi/lo split of a float4 into two packed uint2 (4 bf16 each).
// ---------------------------------------------------------------------------
__device__ __forceinline__ void split4(float4 v, uint2& hi, uint2& lo) {
    __nv_bfloat162 h0 = __floats2bfloat162_rn(v.x, v.y);
    __nv_bfloat162 h1 = __floats2bfloat162_rn(v.z, v.w);
    float2 f0 = __bfloat1622float2(h0);
    float2 f1 = __bfloat1622float2(h1);
    __nv_bfloat162 l0 = __floats2bfloat162_rn(v.x - f0.x, v.y - f0.y);
    __nv_bfloat162 l1 = __floats2bfloat162_rn(v.z - f1.x, v.w - f1.y);
    hi.x = *reinterpret_cast<uint32_t*>(&h0);
    hi.y = *reinterpret_cast<uint32_t*>(&h1);
    lo.x = *reinterpret_cast<uint32_t*>(&l0);
    lo.y = *reinterpret_cast<uint32_t*>(&l1);
}

// ---------------------------------------------------------------------------
// Tensor-core GEMM (R13-proven structure): smem-staged wmma, double buffer,
// reg prefetch. NEW: reads P in fp32 directly (Pr|Pi concat) and converts to
// bf16 hi/lo inline during staging — prep_P kernel deleted (it interfered
// with the MUFU-bound main when run concurrently).
// CTA = 64b x 128j, 8 warps of 32x32 (2x2 frags), 4 stages of KK=32.
// hi*hi + lo*hi + hi*lo, fp32 acc. Grid (8,32)=256 CTAs; disjoint partials.
// ---------------------------------------------------------------------------
__global__ __launch_bounds__(256) void gemm_wmma(const float* __restrict__ Pr,
                                                 const float* __restrict__ Pi) {
    extern __shared__ __nv_bfloat16 sm[];

    int tid  = threadIdx.x;
    int warp = tid >> 5;
    int wb   = (warp >> 2) * 32;
    int wj   = (warp & 3) * 32;
    int j0   = blockIdx.x * 128;
    int k0   = blockIdx.y * (K_TOTAL / KSPLIT);   // 128 per CTA, half-aligned

    const float* P     = (k0 < NUM_NEURONS) ? Pr : Pi;
    int          kbase = (k0 < NUM_NEURONS) ? k0 : k0 - NUM_NEURONS;

    // A staging: 64 rows x 4 chunks of 8 bf16
    int arow = tid >> 2, achk = (tid & 3) * 8;
    const __nv_bfloat16* gAh = g_Ahi + arow * K_TOTAL + k0 + achk;
    const __nv_bfloat16* gAl = g_Alo + arow * K_TOTAL + k0 + achk;
    // B staging: 128 rows, 2 threads/row, 16 contiguous fp32 each
    int brow0 = tid >> 1, bchk0 = (tid & 1) * 16;
    const float* gB = P + (j0 + brow0) * NUM_NEURONS + kbase + bchk0;

    uint32_t aDst = arow * LDM + achk;
    uint32_t bDst = brow0 * LDM + bchk0;

    wmma::fragment<wmma::matrix_a, 16, 16, 16, __nv_bfloat16, wmma::row_major> aH[2], aL[2];
    wmma::fragment<wmma::matrix_b, 16, 16, 16, __nv_bfloat16, wmma::col_major> bH[2], bL[2];
    wmma::fragment<wmma::accumulator, 16, 16, 16, float> c[2][2];
    #pragma unroll
    for (int i = 0; i < 2; i++)
        #pragma unroll
        for (int j = 0; j < 2; j++) wmma::fill_fragment(c[i][j], 0.0f);

    {   // stage 0: global -> smem (convert B inline)
        __nv_bfloat16* st = sm;
        *reinterpret_cast<uint4*>(st + aDst)          = *reinterpret_cast<const uint4*>(gAh);
        *reinterpret_cast<uint4*>(st + OFF_AL + aDst) = *reinterpret_cast<const uint4*>(gAl);
        #pragma unroll
        for (int q = 0; q < 4; q++) {
            float4 v = reinterpret_cast<const float4*>(gB)[q];
            uint2 h, l;
            split4(v, h, l);
            *reinterpret_cast<uint2*>(st + OFF_BH + bDst + q * 4) = h;
            *reinterpret_cast<uint2*>(st + OFF_BL + bDst + q * 4) = l;
        }
    }
    __syncthreads();

    uint4 rAh, rAl;
    uint2 rBh[4], rBl[4];

    for (int s = 0; s < NSTAGE; s++) {
        if (s + 1 < NSTAGE) {             // prefetch next stage; convert B now
            int off = (s + 1) * KK;
            rAh = *reinterpret_cast<const uint4*>(gAh + off);
            rAl = *reinterpret_cast<const uint4*>(gAl + off);
            #pragma unroll
            for (int q = 0; q < 4; q++) {
                float4 v = reinterpret_cast<const float4*>(gB + off)[q];
                split4(v, rBh[q], rBl[q]);
            }
        }

        const __nv_bfloat16* st = sm + (s & 1) * STAGE_EL;
        #pragma unroll
        for (int ks = 0; ks < 2; ks++) {
            int kc = ks * 16;
            wmma::load_matrix_sync(aH[0], st + (wb +  0) * LDM + kc, LDM);
            wmma::load_matrix_sync(aH[1], st + (wb + 16) * LDM + kc, LDM);
            wmma::load_matrix_sync(aL[0], st + OFF_AL + (wb +  0) * LDM + kc, LDM);
            wmma::load_matrix_sync(aL[1], st + OFF_AL + (wb + 16) * LDM + kc, LDM);
            wmma::load_matrix_sync(bH[0], st + OFF_BH + (wj +  0) * LDM + kc, LDM);
            wmma::load_matrix_sync(bH[1], st + OFF_BH + (wj + 16) * LDM + kc, LDM);
            wmma::load_matrix_sync(bL[0], st + OFF_BL + (wj +  0) * LDM + kc, LDM);
            wmma::load_matrix_sync(bL[1], st + OFF_BL + (wj + 16) * LDM + kc, LDM);
            #pragma unroll
            for (int i = 0; i < 2; i++)
                #pragma unroll
                for (int j = 0; j < 2; j++) {
                    wmma::mma_sync(c[i][j], aH[i], bH[j], c[i][j]);
                    wmma::mma_sync(c[i][j], aL[i], bH[j], c[i][j]);
                    wmma::mma_sync(c[i][j], aH[i], bL[j], c[i][j]);
                }
        }

        if (s + 1 < NSTAGE) {
            __syncthreads();
            __nv_bfloat16* dt = sm + ((s + 1) & 1) * STAGE_EL;
            *reinterpret_cast<uint4*>(dt + aDst)          = rAh;
            *reinterpret_cast<uint4*>(dt + OFF_AL + aDst) = rAl;
            #pragma unroll
            for (int q = 0; q < 4; q++) {
                *reinterpret_cast<uint2*>(dt + OFF_BH + bDst + q * 4) = rBh[q];
                *reinterpret_cast<uint2*>(dt + OFF_BL + bDst + q * 4) = rBl[q];
            }
            __syncthreads();
        }
    }

    float* dst = g_part + blockIdx.y * (BATCH * D_MODEL);
    #pragma unroll
    for (int i = 0; i < 2; i++)
        #pragma unroll
        for (int j = 0; j < 2; j++)
            wmma::store_matrix_sync(dst + (wb + i * 16) * D_MODEL + j0 + wj + j * 16,
                                    c[i][j], D_MODEL, wmma::mem_row_major);
}

// ---------------------------------------------------------------------------
// Epilogue: reduce KSPLIT=32 partials + SiLU (R3-proven 256x256 config).
// ---------------------------------------------------------------------------
__global__ __launch_bounds__(256) void epilogue(float* __restrict__ out) {
    int i = blockIdx.x * 256 + threadIdx.x;
    float s = 0.0f;
    #pragma unroll
    for (int ks = 0; ks < KSPLIT; ks++)
        s += g_part[ks * (BATCH * D_MODEL) + i];
    out[i] = s / (1.0f + expf(-s));
}

// ---------------------------------------------------------------------------
// Single stream, no side-stream prep (prep_P interfered with main in R13).
// Inputs: x, t, W, B_p, proj_real_w, proj_imag_w, sin_table, cos_table.
// ---------------------------------------------------------------------------
extern "C" void kernel_launch(void* const* d_in, const int* in_sizes, int n_in,
                              void* d_out, int out_size) {
    const float* x  = (const float*)d_in[0];
    const float* t  = (const float*)d_in[1];
    const float* W  = (const float*)d_in[2];
    const float* Bp = (const float*)d_in[3];
    const float* Pr = (const float*)d_in[4];
    const float* Pi = (const float*)d_in[5];
    float* out = (float*)d_out;

    static bool init = false;
    if (!init) {
        cudaFuncSetAttribute(gemm_wmma, cudaFuncAttributeMaxDynamicSharedMemorySize, SMEM_B);
        init = true;
    }

    prep_x<<<(BATCH * D_MODEL + 255) / 256, 256>>>(x);
    resonant_main<<<NUM_NEURONS / 2, 128>>>(t, W, Bp);
    gemm_wmma<<<dim3(D_MODEL / 128, KSPLIT), 256, SMEM_B>>>(Pr, Pi);
    epilogue<<<(BATCH * D_MODEL + 255) / 256, 256>>>(out);
}